// round 14
// baseline (speedup 1.0000x reference)
#include <cuda_runtime.h>
#include <math.h>

#define BZ 2
#define CHN 96
#define HWSZ 16384              // 128*128
#define PTOT 32768              // B*H*W
#define TSZ 3145728             // C*B*H*W
#define NWD 31
#define SCALE_ATTN 0.2041241452319315f   // 1/sqrt(24)

// ---------------- device scratch (static; no allocations allowed) ----------------
__device__ float g_ln_l[TSZ];           // [c][b][hw]  (c-major)
__device__ float g_ln_h[TSZ];
// fold buffers: 4 window-parity classes per band; class p at offset p*TSZ.
// Windows within a parity class are disjoint -> plain stores, no memset needed
// (uncovered boundary strips are never read thanks to coverage predicates).
__device__ float g_fold_l[4 * TSZ];
__device__ float g_fold_h[4 * TSZ];
__device__ float g_base_l[TSZ];         // [b][c][hw]  (b-major, like inputs/outputs)
__device__ float g_base_h[TSZ];
__device__ float g_qkv_l[288 * PTOT];   // rows: [0,96)=Q  [96,192)=K  [192,288)=V
__device__ float g_qkv_h[288 * PTOT];
__device__ float g_hbuf_l[384 * PTOT];  // MLP hidden (low),  c-major
__device__ float g_hbuf_h[384 * PTOT];  // MLP hidden (high), c-major
__device__ float g_pool[BZ * CHN];
__device__ float g_se[BZ * CHN];
__device__ float g_wl[288 * 96];        // stacked [Wq_l; Wk_l; Wv_l]
__device__ float g_wh[288 * 96];        // stacked [Wq_h; Wk_h; Wv_h]

// ---------------- LayerNorm (per pixel over 96 channels), optional +shift read ----
__global__ void ln_kernel(const float* __restrict__ src, float* __restrict__ dst,
                          const float* __restrict__ g, const float* __restrict__ bb, int shift) {
    int idx = blockIdx.x * 256 + threadIdx.x;      // 0..32767
    int b  = idx >> 14;
    int hw = idx & 16383;
    int h = hw >> 7, w = hw & 127;
    int hs = (h + shift) & 127, ws = (w + shift) & 127;
    const float* sp = src + (size_t)b * CHN * HWSZ + hs * 128 + ws;
    float sum = 0.f, sq = 0.f;
#pragma unroll 8
    for (int c = 0; c < CHN; c++) { float v = sp[(size_t)c * HWSZ]; sum += v; sq += v * v; }
    float mu  = sum * (1.f / 96.f);
    float var = sq * (1.f / 96.f) - mu * mu;
    float rs  = rsqrtf(var + 1e-5f);
    float* dp = dst + (size_t)b * HWSZ + hw;
#pragma unroll 8
    for (int c = 0; c < CHN; c++) {
        float v = sp[(size_t)c * HWSZ];
        dp[(size_t)c * PTOT] = (v - mu) * rs * g[c] + bb[c];
    }
}

// ---------------- SE: global average pool over HW per (b,c) ----------------------
__global__ void pool_kernel(const float* __restrict__ x, float* __restrict__ pool) {
    int bid = blockIdx.x;                 // b*96+c
    int b = bid / CHN, c = bid % CHN;
    const float* p = x + (size_t)c * PTOT + (size_t)b * HWSZ;
    float s = 0.f;
    for (int i = threadIdx.x; i < HWSZ; i += 256) s += p[i];
    __shared__ float red[8];
    for (int o = 16; o; o >>= 1) s += __shfl_xor_sync(0xffffffff, s, o);
    if ((threadIdx.x & 31) == 0) red[threadIdx.x >> 5] = s;
    __syncthreads();
    if (threadIdx.x == 0) {
        float t = 0.f;
        for (int i = 0; i < 8; i++) t += red[i];
        pool[bid] = t * (1.f / HWSZ);
    }
}

// ---------------- SE: squeeze-excite MLP (tiny) -----------------------------------
__global__ void se_kernel(const float* __restrict__ pool, const float* __restrict__ w1,
                          const float* __restrict__ w2, float* __restrict__ se) {
    __shared__ float z[12];               // [b][i][r]
    int t = threadIdx.x;
    if (t < 12) {
        int b = t / 6, rem = t % 6, i = rem >> 1, r = rem & 1;
        float a = 0.f;
        const float* pp = pool + b * 96 + i * 32;
        const float* wp = w1 + i * 64 + r * 32;
        for (int c = 0; c < 32; c++) a += pp[c] * wp[c];
        z[t] = fmaxf(a, 0.f);
    }
    __syncthreads();
    if (t < 192) {
        int b = t / 96, c = t % 96, i = c / 32, cl = c & 31;
        float v = z[b * 6 + i * 2 + 0] * w2[i * 64 + cl * 2 + 0]
                + z[b * 6 + i * 2 + 1] * w2[i * 64 + cl * 2 + 1];
        se[t] = 1.f / (1.f + __expf(-v));
    }
}

// ---------------- tiled GEMM: Y[O][P] = f(W[O][K] @ X[K][P]) ----------------------
// R10-proven: BM=128, BN=64, BK=16; 256 threads; 8x4 micro-tile; 2-stage double
// buffer with register prefetch (one sync per k-tile).
// XMODE: 0 = X c-major (opt per-(b,c) scale)    1 = X b-major
//        2 = X = 4 parity-fold buffers, read at shifted pixel with coverage
//            predicates, summed and scaled by 1/cnt
// YMODE: 0 = plain store c-major                1 = gelu(acc+bias) store c-major
//        2 = b-major: Y = res + acc (+bias) (+ lnadd at shifted pixel, c-major)
template <int XMODE, int YMODE>
__global__ void gemm_kernel(const float* __restrict__ W, const float* __restrict__ X,
                            const float* __restrict__ bias, const float* __restrict__ res,
                            float* __restrict__ Y, const float* __restrict__ scale,
                            const float* __restrict__ lnadd,
                            int O, int K, int shift) {
    __shared__ float Ws[2][16][132];
    __shared__ float Xs[2][16][68];
    int t  = threadIdx.x;
    int og = t >> 4, pg = t & 15;
    int o0 = blockIdx.y * 128;
    int p0 = blockIdx.x * 64;

    float acc[8][4];
#pragma unroll
    for (int i = 0; i < 8; i++)
#pragma unroll
        for (int j = 0; j < 4; j++) acc[i][j] = 0.f;

    float wreg[8], xreg[4];

    auto load_regs = [&](int k0) {
        int kk = t & 15, obase = t >> 4;
#pragma unroll
        for (int r = 0; r < 8; r++) {
            int o = o0 + obase + r * 16;
            wreg[r] = (o < O) ? W[(size_t)o * K + k0 + kk] : 0.f;
        }
        int col = t & 63, kb = t >> 6;
        int p = p0 + col;
        int b = p >> 14, hw = p & 16383;
#pragma unroll
        for (int r = 0; r < 4; r++) {
            int k = k0 + kb + r * 4;
            float v;
            if (XMODE == 0) {
                v = X[(size_t)k * PTOT + p];
                if (scale) v *= scale[b * 96 + k];
            } else if (XMODE == 1) {
                v = X[((size_t)b * CHN + k) * HWSZ + hw];
            } else {
                int h = hw >> 7, w = hw & 127;
                int hs = (h + shift) & 127, wsp = (w + shift) & 127;
                bool hin = (hs >= 4 && hs < 124);   // parity-1 h-windows cover hs
                bool win = (wsp >= 4 && wsp < 124); // parity-1 w-windows cover wsp
                float ic = 1.f / ((hin ? 2.f : 1.f) * (win ? 2.f : 1.f));
                size_t base = (size_t)k * PTOT + (size_t)b * HWSZ + hs * 128 + wsp;
                float s = X[base];                              // parity (0,0)
                if (win)        s += X[base + (size_t)TSZ];     // parity (0,1)
                if (hin)        s += X[base + 2 * (size_t)TSZ]; // parity (1,0)
                if (hin && win) s += X[base + 3 * (size_t)TSZ]; // parity (1,1)
                v = s * ic;
            }
            xreg[r] = v;
        }
    };
    auto store_smem = [&](int buf) {
        int kk = t & 15, obase = t >> 4;
#pragma unroll
        for (int r = 0; r < 8; r++) Ws[buf][kk][obase + r * 16] = wreg[r];
        int col = t & 63, kb = t >> 6;
#pragma unroll
        for (int r = 0; r < 4; r++) Xs[buf][kb + r * 4][col] = xreg[r];
    };

    load_regs(0);
    store_smem(0);
    __syncthreads();

    int nk = K >> 4;
    for (int it = 0; it < nk; it++) {
        int cur = it & 1;
        if (it + 1 < nk) load_regs((it + 1) << 4);   // LDGs overlap the FFMAs below
#pragma unroll
        for (int kk = 0; kk < 16; kk++) {
            float4 a0 = *(const float4*)&Ws[cur][kk][og * 8];
            float4 a1 = *(const float4*)&Ws[cur][kk][og * 8 + 4];
            float4 bv = *(const float4*)&Xs[cur][kk][pg * 4];
            float av[8] = {a0.x, a0.y, a0.z, a0.w, a1.x, a1.y, a1.z, a1.w};
            float bw[4] = {bv.x, bv.y, bv.z, bv.w};
#pragma unroll
            for (int i = 0; i < 8; i++)
#pragma unroll
                for (int j = 0; j < 4; j++) acc[i][j] += av[i] * bw[j];
        }
        if (it + 1 < nk) store_smem(cur ^ 1);
        __syncthreads();
    }

#pragma unroll
    for (int i = 0; i < 8; i++) {
        int o = o0 + og * 8 + i;
        if (o >= O) continue;
#pragma unroll
        for (int j = 0; j < 4; j++) {
            int p = p0 + pg * 4 + j;
            float v = acc[i][j];
            if (YMODE == 0) {
                Y[(size_t)o * PTOT + p] = v;
            } else if (YMODE == 1) {
                v += bias[o];
                Y[(size_t)o * PTOT + p] = 0.5f * v * (1.f + erff(v * 0.70710678118654752f));
            } else {
                int b = p >> 14, hw = p & 16383;
                size_t a = ((size_t)b * CHN + o) * HWSZ + hw;
                if (bias) v += bias[o];
                if (lnadd) {
                    // _win returns LN(x) + proj(out); add LN at the same shifted pixel
                    int h = hw >> 7, w = hw & 127;
                    int hs2 = (h + shift) & 127, ws2 = (w + shift) & 127;
                    v += lnadd[(size_t)o * PTOT + (size_t)b * HWSZ + hs2 * 128 + ws2];
                }
                Y[a] = res[a] + v;
            }
        }
    }
}

// ---------------- window cross-attention -------------------------------------------
// One block = (window, batch, dir); loops over 4 heads.
// q,k staged transposed [d][n] (pitch 68); v [m][d] (pitch 28); Ss pitch 65.
// Output written with PLAIN stores into the window's parity-class fold buffer
// (windows within a parity class are disjoint -> no atomics needed).
__global__ void attn_kernel(const float* __restrict__ qkv_l, const float* __restrict__ qkv_h,
                            float* __restrict__ fold_l, float* __restrict__ fold_h) {
    __shared__ float qst[24 * 68];  // [d][n]
    __shared__ float kst[24 * 68];  // [d][m]
    __shared__ float vs[64 * 28];   // [m][d]
    __shared__ float Ss[64 * 65];   // [n][m] pitch 65
    int t = threadIdx.x;
    int wid = blockIdx.x;           // 0..960
    int b = blockIdx.y;
    int dir = blockIdx.z;
    int wh = wid / NWD, ww = wid % NWD;
    int h0 = wh * 4, w0 = ww * 4;
    int pixbase = b * HWSZ + h0 * 128 + w0;
    int parity = (wh & 1) * 2 + (ww & 1);

    const float* qsrc  = dir ? qkv_h : qkv_l;   // query side
    const float* kvsrc = dir ? qkv_l : qkv_h;   // key/value side
    float* fdst = (dir ? fold_h : fold_l) + (size_t)parity * TSZ;

    for (int hd = 0; hd < 4; hd++) {
        int rbase = hd * 24;
        // gather q,k (transposed) and v (row-major) — 6 elements per thread each
        for (int idx = t; idx < 1536; idx += 256) {
            int d = idx >> 6, n = idx & 63;
            int pix = pixbase + ((n >> 3) << 7) + (n & 7);
            qst[d * 68 + n] = qsrc[(size_t)(rbase + d) * PTOT + pix];        // stride-1 store
            kst[d * 68 + n] = kvsrc[(size_t)(96 + rbase + d) * PTOT + pix];  // stride-1 store
            vs[n * 28 + d]  = kvsrc[(size_t)(192 + rbase + d) * PTOT + pix];
        }
        __syncthreads();
        // scores S[n][m] = scale * sum_d q[d][n] k[d][m]; outer product per d
        {
            int nb = (t >> 4) << 2, mb = (t & 15) << 2;
            float acc[4][4];
#pragma unroll
            for (int i = 0; i < 4; i++)
#pragma unroll
                for (int j = 0; j < 4; j++) acc[i][j] = 0.f;
#pragma unroll 6
            for (int dc = 0; dc < 24; dc++) {
                float4 qv = *(const float4*)&qst[dc * 68 + nb];   // CF float4
                float4 kv = *(const float4*)&kst[dc * 68 + mb];   // CF float4
                float qa[4] = {qv.x, qv.y, qv.z, qv.w};
                float ka[4] = {kv.x, kv.y, kv.z, kv.w};
#pragma unroll
                for (int i = 0; i < 4; i++)
#pragma unroll
                    for (int j = 0; j < 4; j++) acc[i][j] += qa[i] * ka[j];
            }
#pragma unroll
            for (int i = 0; i < 4; i++)
#pragma unroll
                for (int j = 0; j < 4; j++)
                    Ss[(nb + i) * 65 + mb + j] = acc[i][j] * SCALE_ATTN;
        }
        __syncthreads();
        // softmax over m: 4 threads per row, shfl-reduce within lane-quad
        {
            int row = t >> 2, sub = t & 3;
            float* r = &Ss[row * 65];
            int m0 = sub * 16;
            float mx = -1e30f;
#pragma unroll
            for (int m = 0; m < 16; m++) mx = fmaxf(mx, r[m0 + m]);
            mx = fmaxf(mx, __shfl_xor_sync(0xffffffffu, mx, 1));
            mx = fmaxf(mx, __shfl_xor_sync(0xffffffffu, mx, 2));
            float sum = 0.f;
#pragma unroll
            for (int m = 0; m < 16; m++) {
                float e = __expf(r[m0 + m] - mx);
                r[m0 + m] = e; sum += e;
            }
            sum += __shfl_xor_sync(0xffffffffu, sum, 1);
            sum += __shfl_xor_sync(0xffffffffu, sum, 2);
            float inv = 1.f / sum;
#pragma unroll
            for (int m = 0; m < 16; m++) r[m0 + m] *= inv;
        }
        __syncthreads();
        // O[d][n] = sum_m S[n][m] v[m][d]; 192 threads: (n, dgroup of 8)
        if (t < 192) {
            int n = t & 63, dg = t >> 6;
            float a8[8];
#pragma unroll
            for (int i = 0; i < 8; i++) a8[i] = 0.f;
            const float* srow = &Ss[n * 65];
#pragma unroll 4
            for (int m = 0; m < 64; m++) {
                float s = srow[m];                       // CF (stride ≡ 1 bank)
                const float* vp = &vs[m * 28 + dg * 8];  // broadcast
#pragma unroll
                for (int i = 0; i < 8; i++) a8[i] += s * vp[i];
            }
            int pix = pixbase + ((n >> 3) << 7) + (n & 7);
#pragma unroll
            for (int i = 0; i < 8; i++)
                fdst[(size_t)(rbase + dg * 8 + i) * PTOT + pix] = a8[i];   // plain STG
        }
        __syncthreads();
    }
}

// -------------------------------- host launcher -----------------------------------
extern "C" void kernel_launch(void* const* d_in, const int* in_sizes, int n_in,
                              void* d_out, int out_size) {
    const float* low    = (const float*)d_in[0];
    const float* high   = (const float*)d_in[1];
    const float* ln1_g  = (const float*)d_in[2];
    const float* ln1_b  = (const float*)d_in[3];
    const float* ln2_g  = (const float*)d_in[4];
    const float* ln2_b  = (const float*)d_in[5];
    const float* se_w1  = (const float*)d_in[6];
    const float* se_w2  = (const float*)d_in[7];
    const float* wq_l   = (const float*)d_in[8];
    const float* wk_h   = (const float*)d_in[9];
    const float* wv_h   = (const float*)d_in[10];
    const float* wq_h   = (const float*)d_in[11];
    const float* wk_l   = (const float*)d_in[12];
    const float* wv_l   = (const float*)d_in[13];
    const float* wp_l   = (const float*)d_in[14];
    const float* wp_h   = (const float*)d_in[15];
    const float* mlp_w1 = (const float*)d_in[16];
    const float* mlp_b1 = (const float*)d_in[17];
    const float* mlp_w2 = (const float*)d_in[18];
    const float* mlp_b2 = (const float*)d_in[19];

    float* out_l = (float*)d_out;
    float* out_h = out_l + (size_t)TSZ;

    float *p_ln_l, *p_ln_h, *p_fold_l, *p_fold_h, *p_base_l, *p_base_h;
    float *p_qkv_l, *p_qkv_h, *p_hbuf_l, *p_hbuf_h, *p_pool, *p_se, *p_wl, *p_wh;
    cudaGetSymbolAddress((void**)&p_ln_l,   g_ln_l);
    cudaGetSymbolAddress((void**)&p_ln_h,   g_ln_h);
    cudaGetSymbolAddress((void**)&p_fold_l, g_fold_l);
    cudaGetSymbolAddress((void**)&p_fold_h, g_fold_h);
    cudaGetSymbolAddress((void**)&p_base_l, g_base_l);
    cudaGetSymbolAddress((void**)&p_base_h, g_base_h);
    cudaGetSymbolAddress((void**)&p_qkv_l,  g_qkv_l);
    cudaGetSymbolAddress((void**)&p_qkv_h,  g_qkv_h);
    cudaGetSymbolAddress((void**)&p_hbuf_l, g_hbuf_l);
    cudaGetSymbolAddress((void**)&p_hbuf_h, g_hbuf_h);
    cudaGetSymbolAddress((void**)&p_pool,   g_pool);
    cudaGetSymbolAddress((void**)&p_se,     g_se);
    cudaGetSymbolAddress((void**)&p_wl,     g_wl);
    cudaGetSymbolAddress((void**)&p_wh,     g_wh);

    const size_t WB = 96 * 96 * sizeof(float);
    // stacked projection weights: [Q;K;V]
    cudaMemcpyAsync(p_wl,          wq_l, WB, cudaMemcpyDeviceToDevice, 0);
    cudaMemcpyAsync(p_wl + 9216,   wk_l, WB, cudaMemcpyDeviceToDevice, 0);
    cudaMemcpyAsync(p_wl + 18432,  wv_l, WB, cudaMemcpyDeviceToDevice, 0);
    cudaMemcpyAsync(p_wh,          wq_h, WB, cudaMemcpyDeviceToDevice, 0);
    cudaMemcpyAsync(p_wh + 9216,   wk_h, WB, cudaMemcpyDeviceToDevice, 0);
    cudaMemcpyAsync(p_wh + 18432,  wv_h, WB, cudaMemcpyDeviceToDevice, 0);

    dim3 gP1(512, 1), gP3(512, 3), gAttn(961, 2, 2);

    // ================= stage 1 (no shift) =================
    ln_kernel<<<128, 256>>>(low,  p_ln_l, ln1_g, ln1_b, 0);
    ln_kernel<<<128, 256>>>(high, p_ln_h, ln1_g, ln1_b, 0);
    gemm_kernel<0, 0><<<gP3, 256>>>(p_wl, p_ln_l, nullptr, nullptr, p_qkv_l, nullptr, nullptr, 288, 96, 0);
    pool_kernel<<<192, 256>>>(p_ln_h, p_pool);
    se_kernel<<<1, 256>>>(p_pool, se_w1, se_w2, p_se);
    gemm_kernel<0, 0><<<gP3, 256>>>(p_wh, p_ln_h, nullptr, nullptr, p_qkv_h, p_se, nullptr, 288, 96, 0);
    attn_kernel<<<gAttn, 256>>>(p_qkv_l, p_qkv_h, p_fold_l, p_fold_h);
    // base = input + LN(input) + proj(sum of parity folds / cnt)
    gemm_kernel<2, 2><<<gP1, 256>>>(wp_l, p_fold_l, nullptr, low,  p_base_l, nullptr, p_ln_l, 96, 96, 0);
    gemm_kernel<2, 2><<<gP1, 256>>>(wp_h, p_fold_h, nullptr, high, p_base_h, nullptr, p_ln_h, 96, 96, 0);

    // ================= stage 2 (shifted by 4) =================
    ln_kernel<<<128, 256>>>(p_base_l, p_ln_l, ln2_g, ln2_b, 4);
    ln_kernel<<<128, 256>>>(p_base_h, p_ln_h, ln2_g, ln2_b, 4);
    pool_kernel<<<192, 256>>>(p_ln_h, p_pool);
    se_kernel<<<1, 256>>>(p_pool, se_w1, se_w2, p_se);
    gemm_kernel<0, 0><<<gP3, 256>>>(p_wl, p_ln_l, nullptr, nullptr, p_qkv_l, nullptr, nullptr, 288, 96, 0);
    gemm_kernel<0, 0><<<gP3, 256>>>(p_wh, p_ln_h, nullptr, nullptr, p_qkv_h, p_se, nullptr, 288, 96, 0);
    attn_kernel<<<gAttn, 256>>>(p_qkv_l, p_qkv_h, p_fold_l, p_fold_h);
    // un-shift: dst(h,w) = base + (LN(ls) + proj(folds/cnt))[(h-4)%128, (w-4)%128]
    gemm_kernel<2, 2><<<gP1, 256>>>(wp_l, p_fold_l, nullptr, p_base_l, out_l, nullptr, p_ln_l, 96, 96, 124);
    gemm_kernel<2, 2><<<gP1, 256>>>(wp_h, p_fold_h, nullptr, p_base_h, out_h, nullptr, p_ln_h, 96, 96, 124);

    // ================= stage 3: per-pixel MLP with residual =================
    gemm_kernel<1, 1><<<gP3, 256>>>(mlp_w1, out_l, mlp_b1, nullptr, p_hbuf_l, nullptr, nullptr, 384, 96, 0);
    gemm_kernel<1, 1><<<gP3, 256>>>(mlp_w1, out_h, mlp_b1, nullptr, p_hbuf_h, nullptr, nullptr, 384, 96, 0);
    gemm_kernel<0, 2><<<gP1, 256>>>(mlp_w2, p_hbuf_l, mlp_b2, out_l, out_l, nullptr, nullptr, 96, 384, 0);
    gemm_kernel<0, 2><<<gP1, 256>>>(mlp_w2, p_hbuf_h, mlp_b2, out_h, out_h, nullptr, nullptr, 96, 384, 0);
}

// round 15
// speedup vs baseline: 1.0933x; 1.0933x over previous
#include <cuda_runtime.h>
#include <math.h>

#define BZ 2
#define CHN 96
#define HWSZ 16384              // 128*128
#define PTOT 32768              // B*H*W
#define TSZ 3145728             // C*B*H*W
#define NWD 31
#define SCALE_ATTN 0.2041241452319315f   // 1/sqrt(24)

// ---------------- device scratch (static; no allocations allowed) ----------------
__device__ float g_ln_l[TSZ];           // [c][b][hw]  (c-major)
__device__ float g_ln_h[TSZ];
__device__ float g_fold_l[TSZ];
__device__ float g_fold_h[TSZ];
__device__ float g_base_l[TSZ];         // [b][c][hw]  (b-major, like inputs/outputs)
__device__ float g_base_h[TSZ];
__device__ float g_qkv_l[288 * PTOT];   // rows: [0,96)=Q  [96,192)=K  [192,288)=V
__device__ float g_qkv_h[288 * PTOT];
__device__ float g_hbuf_l[384 * PTOT];  // MLP hidden (low),  c-major
__device__ float g_hbuf_h[384 * PTOT];  // MLP hidden (high), c-major
__device__ float g_pool[BZ * CHN];
__device__ float g_se[BZ * CHN];
__device__ float g_wl[288 * 96];        // stacked [Wq_l; Wk_l; Wv_l]
__device__ float g_wh[288 * 96];        // stacked [Wq_h; Wk_h; Wv_h]

// ---------------- LayerNorm (per pixel over 96 channels), optional +shift read ----
__global__ void ln_kernel(const float* __restrict__ src, float* __restrict__ dst,
                          const float* __restrict__ g, const float* __restrict__ bb, int shift) {
    int idx = blockIdx.x * 256 + threadIdx.x;      // 0..32767
    int b  = idx >> 14;
    int hw = idx & 16383;
    int h = hw >> 7, w = hw & 127;
    int hs = (h + shift) & 127, ws = (w + shift) & 127;
    const float* sp = src + (size_t)b * CHN * HWSZ + hs * 128 + ws;
    float sum = 0.f, sq = 0.f;
#pragma unroll 8
    for (int c = 0; c < CHN; c++) { float v = sp[(size_t)c * HWSZ]; sum += v; sq += v * v; }
    float mu  = sum * (1.f / 96.f);
    float var = sq * (1.f / 96.f) - mu * mu;
    float rs  = rsqrtf(var + 1e-5f);
    float* dp = dst + (size_t)b * HWSZ + hw;
#pragma unroll 8
    for (int c = 0; c < CHN; c++) {
        float v = sp[(size_t)c * HWSZ];
        dp[(size_t)c * PTOT] = (v - mu) * rs * g[c] + bb[c];
    }
}

// ---------------- SE: global average pool over HW per (b,c) ----------------------
__global__ void pool_kernel(const float* __restrict__ x, float* __restrict__ pool) {
    int bid = blockIdx.x;                 // b*96+c
    int b = bid / CHN, c = bid % CHN;
    const float* p = x + (size_t)c * PTOT + (size_t)b * HWSZ;
    float s = 0.f;
    for (int i = threadIdx.x; i < HWSZ; i += 256) s += p[i];
    __shared__ float red[8];
    for (int o = 16; o; o >>= 1) s += __shfl_xor_sync(0xffffffff, s, o);
    if ((threadIdx.x & 31) == 0) red[threadIdx.x >> 5] = s;
    __syncthreads();
    if (threadIdx.x == 0) {
        float t = 0.f;
        for (int i = 0; i < 8; i++) t += red[i];
        pool[bid] = t * (1.f / HWSZ);
    }
}

// ---------------- SE: squeeze-excite MLP (tiny) -----------------------------------
__global__ void se_kernel(const float* __restrict__ pool, const float* __restrict__ w1,
                          const float* __restrict__ w2, float* __restrict__ se) {
    __shared__ float z[12];               // [b][i][r]
    int t = threadIdx.x;
    if (t < 12) {
        int b = t / 6, rem = t % 6, i = rem >> 1, r = rem & 1;
        float a = 0.f;
        const float* pp = pool + b * 96 + i * 32;
        const float* wp = w1 + i * 64 + r * 32;
        for (int c = 0; c < 32; c++) a += pp[c] * wp[c];
        z[t] = fmaxf(a, 0.f);
    }
    __syncthreads();
    if (t < 192) {
        int b = t / 96, c = t % 96, i = c / 32, cl = c & 31;
        float v = z[b * 6 + i * 2 + 0] * w2[i * 64 + cl * 2 + 0]
                + z[b * 6 + i * 2 + 1] * w2[i * 64 + cl * 2 + 1];
        se[t] = 1.f / (1.f + __expf(-v));
    }
}

// ---------------- tiled GEMM: Y[O][P] = f(W[O][K] @ X[K][P]) ----------------------
// R10-proven: BM=128, BN=64, BK=16; 256 threads; 8x4 micro-tile; 2-stage double
// buffer with register prefetch (one sync per k-tile).
// XMODE: 0 = X c-major (opt per-(b,c) scale)    1 = X b-major
//        2 = X c-major read at shifted pixel, scaled by 1/cnt (window fold combine)
// YMODE: 0 = plain store c-major                1 = gelu(acc+bias) store c-major
//        2 = b-major: Y = res + acc (+bias) (+ lnadd at shifted pixel, c-major)
template <int XMODE, int YMODE>
__global__ void gemm_kernel(const float* __restrict__ W, const float* __restrict__ X,
                            const float* __restrict__ bias, const float* __restrict__ res,
                            float* __restrict__ Y, const float* __restrict__ scale,
                            const float* __restrict__ lnadd,
                            int O, int K, int shift) {
    __shared__ float Ws[2][16][132];
    __shared__ float Xs[2][16][68];
    int t  = threadIdx.x;
    int og = t >> 4, pg = t & 15;
    int o0 = blockIdx.y * 128;
    int p0 = blockIdx.x * 64;

    float acc[8][4];
#pragma unroll
    for (int i = 0; i < 8; i++)
#pragma unroll
        for (int j = 0; j < 4; j++) acc[i][j] = 0.f;

    float wreg[8], xreg[4];

    auto load_regs = [&](int k0) {
        int kk = t & 15, obase = t >> 4;
#pragma unroll
        for (int r = 0; r < 8; r++) {
            int o = o0 + obase + r * 16;
            wreg[r] = (o < O) ? W[(size_t)o * K + k0 + kk] : 0.f;
        }
        int col = t & 63, kb = t >> 6;
        int p = p0 + col;
        int b = p >> 14, hw = p & 16383;
#pragma unroll
        for (int r = 0; r < 4; r++) {
            int k = k0 + kb + r * 4;
            float v;
            if (XMODE == 0) {
                v = X[(size_t)k * PTOT + p];
                if (scale) v *= scale[b * 96 + k];
            } else if (XMODE == 1) {
                v = X[((size_t)b * CHN + k) * HWSZ + hw];
            } else {
                int h = hw >> 7, w = hw & 127;
                int hs = (h + shift) & 127, wsp = (w + shift) & 127;
                int ch2 = (hs < 4 || hs >= 124) ? 1 : 2;
                int cw2 = (wsp < 4 || wsp >= 124) ? 1 : 2;
                float ic = 1.f / (float)(ch2 * cw2);
                v = X[(size_t)k * PTOT + (size_t)b * HWSZ + hs * 128 + wsp] * ic;
            }
            xreg[r] = v;
        }
    };
    auto store_smem = [&](int buf) {
        int kk = t & 15, obase = t >> 4;
#pragma unroll
        for (int r = 0; r < 8; r++) Ws[buf][kk][obase + r * 16] = wreg[r];
        int col = t & 63, kb = t >> 6;
#pragma unroll
        for (int r = 0; r < 4; r++) Xs[buf][kb + r * 4][col] = xreg[r];
    };

    load_regs(0);
    store_smem(0);
    __syncthreads();

    int nk = K >> 4;
    for (int it = 0; it < nk; it++) {
        int cur = it & 1;
        if (it + 1 < nk) load_regs((it + 1) << 4);   // LDGs overlap the FFMAs below
#pragma unroll
        for (int kk = 0; kk < 16; kk++) {
            float4 a0 = *(const float4*)&Ws[cur][kk][og * 8];
            float4 a1 = *(const float4*)&Ws[cur][kk][og * 8 + 4];
            float4 bv = *(const float4*)&Xs[cur][kk][pg * 4];
            float av[8] = {a0.x, a0.y, a0.z, a0.w, a1.x, a1.y, a1.z, a1.w};
            float bw[4] = {bv.x, bv.y, bv.z, bv.w};
#pragma unroll
            for (int i = 0; i < 8; i++)
#pragma unroll
                for (int j = 0; j < 4; j++) acc[i][j] += av[i] * bw[j];
        }
        if (it + 1 < nk) store_smem(cur ^ 1);
        __syncthreads();
    }

#pragma unroll
    for (int i = 0; i < 8; i++) {
        int o = o0 + og * 8 + i;
        if (o >= O) continue;
#pragma unroll
        for (int j = 0; j < 4; j++) {
            int p = p0 + pg * 4 + j;
            float v = acc[i][j];
            if (YMODE == 0) {
                Y[(size_t)o * PTOT + p] = v;
            } else if (YMODE == 1) {
                v += bias[o];
                Y[(size_t)o * PTOT + p] = 0.5f * v * (1.f + erff(v * 0.70710678118654752f));
            } else {
                int b = p >> 14, hw = p & 16383;
                size_t a = ((size_t)b * CHN + o) * HWSZ + hw;
                if (bias) v += bias[o];
                if (lnadd) {
                    // _win returns LN(x) + proj(out); add LN at the same shifted pixel
                    int h = hw >> 7, w = hw & 127;
                    int hs2 = (h + shift) & 127, ws2 = (w + shift) & 127;
                    v += lnadd[(size_t)o * PTOT + (size_t)b * HWSZ + hs2 * 128 + ws2];
                }
                Y[a] = res[a] + v;
            }
        }
    }
}

// ---------------- window cross-attention -------------------------------------------
// One block = (window, batch, dir, head): blockIdx.z = dir*4 + head.
// q,k staged transposed [d][n] (pitch 68); v [m][d] (pitch 28); Ss pitch 65.
// SV uses all 256 threads: 4 d-groups of 6. Fold output via atomicAdd (R11-proven).
__global__ void attn_kernel(const float* __restrict__ qkv_l, const float* __restrict__ qkv_h,
                            float* __restrict__ fold_l, float* __restrict__ fold_h) {
    __shared__ float qst[24 * 68];  // [d][n]
    __shared__ float kst[24 * 68];  // [d][m]
    __shared__ float vs[64 * 28];   // [m][d]
    __shared__ float Ss[64 * 65];   // [n][m] pitch 65
    int t = threadIdx.x;
    int wid = blockIdx.x;           // 0..960
    int b = blockIdx.y;
    int dir = blockIdx.z >> 2;
    int hd  = blockIdx.z & 3;
    int h0 = (wid / NWD) * 4, w0 = (wid % NWD) * 4;
    int pixbase = b * HWSZ + h0 * 128 + w0;
    int rbase = hd * 24;

    const float* qsrc  = dir ? qkv_h : qkv_l;   // query side
    const float* kvsrc = dir ? qkv_l : qkv_h;   // key/value side
    float* fdst = dir ? fold_h : fold_l;

    // gather q,k (transposed) and v (row-major) — 6 elements per thread each
    for (int idx = t; idx < 1536; idx += 256) {
        int d = idx >> 6, n = idx & 63;
        int pix = pixbase + ((n >> 3) << 7) + (n & 7);
        qst[d * 68 + n] = qsrc[(size_t)(rbase + d) * PTOT + pix];        // stride-1 store
        kst[d * 68 + n] = kvsrc[(size_t)(96 + rbase + d) * PTOT + pix];  // stride-1 store
        vs[n * 28 + d]  = kvsrc[(size_t)(192 + rbase + d) * PTOT + pix];
    }
    __syncthreads();
    // scores S[n][m] = scale * sum_d q[d][n] k[d][m]; outer product per d
    {
        int nb = (t >> 4) << 2, mb = (t & 15) << 2;
        float acc[4][4];
#pragma unroll
        for (int i = 0; i < 4; i++)
#pragma unroll
            for (int j = 0; j < 4; j++) acc[i][j] = 0.f;
#pragma unroll 6
        for (int dc = 0; dc < 24; dc++) {
            float4 qv = *(const float4*)&qst[dc * 68 + nb];   // CF float4
            float4 kv = *(const float4*)&kst[dc * 68 + mb];   // CF float4
            float qa[4] = {qv.x, qv.y, qv.z, qv.w};
            float ka[4] = {kv.x, kv.y, kv.z, kv.w};
#pragma unroll
            for (int i = 0; i < 4; i++)
#pragma unroll
                for (int j = 0; j < 4; j++) acc[i][j] += qa[i] * ka[j];
        }
#pragma unroll
        for (int i = 0; i < 4; i++)
#pragma unroll
            for (int j = 0; j < 4; j++)
                Ss[(nb + i) * 65 + mb + j] = acc[i][j] * SCALE_ATTN;
    }
    __syncthreads();
    // softmax over m: 4 threads per row, shfl-reduce within lane-quad
    {
        int row = t >> 2, sub = t & 3;
        float* r = &Ss[row * 65];
        int m0 = sub * 16;
        float mx = -1e30f;
#pragma unroll
        for (int m = 0; m < 16; m++) mx = fmaxf(mx, r[m0 + m]);
        mx = fmaxf(mx, __shfl_xor_sync(0xffffffffu, mx, 1));
        mx = fmaxf(mx, __shfl_xor_sync(0xffffffffu, mx, 2));
        float sum = 0.f;
#pragma unroll
        for (int m = 0; m < 16; m++) {
            float e = __expf(r[m0 + m] - mx);
            r[m0 + m] = e; sum += e;
        }
        sum += __shfl_xor_sync(0xffffffffu, sum, 1);
        sum += __shfl_xor_sync(0xffffffffu, sum, 2);
        float inv = 1.f / sum;
#pragma unroll
        for (int m = 0; m < 16; m++) r[m0 + m] *= inv;
    }
    __syncthreads();
    // O[d][n] = sum_m S[n][m] v[m][d]; all 256 threads: (n, dgroup of 6)
    {
        int n = t & 63, dg = t >> 6;    // dg 0..3, d range dg*6..dg*6+5
        float a6[6];
#pragma unroll
        for (int i = 0; i < 6; i++) a6[i] = 0.f;
        const float* srow = &Ss[n * 65];
#pragma unroll 4
        for (int m = 0; m < 64; m++) {
            float s = srow[m];                       // CF (stride ≡ 1 bank)
            const float* vp = &vs[m * 28 + dg * 6];  // broadcast within warp
#pragma unroll
            for (int i = 0; i < 6; i++) a6[i] += s * vp[i];
        }
        int pix = pixbase + ((n >> 3) << 7) + (n & 7);
#pragma unroll
        for (int i = 0; i < 6; i++)
            atomicAdd(&fdst[(size_t)(rbase + dg * 6 + i) * PTOT + pix], a6[i]);
    }
}

// -------------------------------- host launcher -----------------------------------
extern "C" void kernel_launch(void* const* d_in, const int* in_sizes, int n_in,
                              void* d_out, int out_size) {
    const float* low    = (const float*)d_in[0];
    const float* high   = (const float*)d_in[1];
    const float* ln1_g  = (const float*)d_in[2];
    const float* ln1_b  = (const float*)d_in[3];
    const float* ln2_g  = (const float*)d_in[4];
    const float* ln2_b  = (const float*)d_in[5];
    const float* se_w1  = (const float*)d_in[6];
    const float* se_w2  = (const float*)d_in[7];
    const float* wq_l   = (const float*)d_in[8];
    const float* wk_h   = (const float*)d_in[9];
    const float* wv_h   = (const float*)d_in[10];
    const float* wq_h   = (const float*)d_in[11];
    const float* wk_l   = (const float*)d_in[12];
    const float* wv_l   = (const float*)d_in[13];
    const float* wp_l   = (const float*)d_in[14];
    const float* wp_h   = (const float*)d_in[15];
    const float* mlp_w1 = (const float*)d_in[16];
    const float* mlp_b1 = (const float*)d_in[17];
    const float* mlp_w2 = (const float*)d_in[18];
    const float* mlp_b2 = (const float*)d_in[19];

    float* out_l = (float*)d_out;
    float* out_h = out_l + (size_t)TSZ;

    float *p_ln_l, *p_ln_h, *p_fold_l, *p_fold_h, *p_base_l, *p_base_h;
    float *p_qkv_l, *p_qkv_h, *p_hbuf_l, *p_hbuf_h, *p_pool, *p_se, *p_wl, *p_wh;
    cudaGetSymbolAddress((void**)&p_ln_l,   g_ln_l);
    cudaGetSymbolAddress((void**)&p_ln_h,   g_ln_h);
    cudaGetSymbolAddress((void**)&p_fold_l, g_fold_l);
    cudaGetSymbolAddress((void**)&p_fold_h, g_fold_h);
    cudaGetSymbolAddress((void**)&p_base_l, g_base_l);
    cudaGetSymbolAddress((void**)&p_base_h, g_base_h);
    cudaGetSymbolAddress((void**)&p_qkv_l,  g_qkv_l);
    cudaGetSymbolAddress((void**)&p_qkv_h,  g_qkv_h);
    cudaGetSymbolAddress((void**)&p_hbuf_l, g_hbuf_l);
    cudaGetSymbolAddress((void**)&p_hbuf_h, g_hbuf_h);
    cudaGetSymbolAddress((void**)&p_pool,   g_pool);
    cudaGetSymbolAddress((void**)&p_se,     g_se);
    cudaGetSymbolAddress((void**)&p_wl,     g_wl);
    cudaGetSymbolAddress((void**)&p_wh,     g_wh);

    const size_t WB = 96 * 96 * sizeof(float);
    // stacked projection weights: [Q;K;V]
    cudaMemcpyAsync(p_wl,          wq_l, WB, cudaMemcpyDeviceToDevice, 0);
    cudaMemcpyAsync(p_wl + 9216,   wk_l, WB, cudaMemcpyDeviceToDevice, 0);
    cudaMemcpyAsync(p_wl + 18432,  wv_l, WB, cudaMemcpyDeviceToDevice, 0);
    cudaMemcpyAsync(p_wh,          wq_h, WB, cudaMemcpyDeviceToDevice, 0);
    cudaMemcpyAsync(p_wh + 9216,   wk_h, WB, cudaMemcpyDeviceToDevice, 0);
    cudaMemcpyAsync(p_wh + 18432,  wv_h, WB, cudaMemcpyDeviceToDevice, 0);

    cudaMemsetAsync(p_fold_l, 0, (size_t)TSZ * sizeof(float), 0);
    cudaMemsetAsync(p_fold_h, 0, (size_t)TSZ * sizeof(float), 0);

    dim3 gP1(512, 1), gP3(512, 3), gAttn(961, 2, 8);

    // ================= stage 1 (no shift) =================
    ln_kernel<<<128, 256>>>(low,  p_ln_l, ln1_g, ln1_b, 0);
    ln_kernel<<<128, 256>>>(high, p_ln_h, ln1_g, ln1_b, 0);
    gemm_kernel<0, 0><<<gP3, 256>>>(p_wl, p_ln_l, nullptr, nullptr, p_qkv_l, nullptr, nullptr, 288, 96, 0);
    pool_kernel<<<192, 256>>>(p_ln_h, p_pool);
    se_kernel<<<1, 256>>>(p_pool, se_w1, se_w2, p_se);
    gemm_kernel<0, 0><<<gP3, 256>>>(p_wh, p_ln_h, nullptr, nullptr, p_qkv_h, p_se, nullptr, 288, 96, 0);
    attn_kernel<<<gAttn, 256>>>(p_qkv_l, p_qkv_h, p_fold_l, p_fold_h);
    // base = input + LN(input) + proj(fold/cnt)
    gemm_kernel<2, 2><<<gP1, 256>>>(wp_l, p_fold_l, nullptr, low,  p_base_l, nullptr, p_ln_l, 96, 96, 0);
    gemm_kernel<2, 2><<<gP1, 256>>>(wp_h, p_fold_h, nullptr, high, p_base_h, nullptr, p_ln_h, 96, 96, 0);

    // ================= stage 2 (shifted by 4) =================
    ln_kernel<<<128, 256>>>(p_base_l, p_ln_l, ln2_g, ln2_b, 4);
    ln_kernel<<<128, 256>>>(p_base_h, p_ln_h, ln2_g, ln2_b, 4);
    pool_kernel<<<192, 256>>>(p_ln_h, p_pool);
    se_kernel<<<1, 256>>>(p_pool, se_w1, se_w2, p_se);
    gemm_kernel<0, 0><<<gP3, 256>>>(p_wl, p_ln_l, nullptr, nullptr, p_qkv_l, nullptr, nullptr, 288, 96, 0);
    gemm_kernel<0, 0><<<gP3, 256>>>(p_wh, p_ln_h, nullptr, nullptr, p_qkv_h, p_se, nullptr, 288, 96, 0);
    cudaMemsetAsync(p_fold_l, 0, (size_t)TSZ * sizeof(float), 0);
    cudaMemsetAsync(p_fold_h, 0, (size_t)TSZ * sizeof(float), 0);
    attn_kernel<<<gAttn, 256>>>(p_qkv_l, p_qkv_h, p_fold_l, p_fold_h);
    // un-shift: dst(h,w) = base + (LN(ls) + proj(fold/cnt))[(h-4)%128, (w-4)%128]
    gemm_kernel<2, 2><<<gP1, 256>>>(wp_l, p_fold_l, nullptr, p_base_l, out_l, nullptr, p_ln_l, 96, 96, 124);
    gemm_kernel<2, 2><<<gP1, 256>>>(wp_h, p_fold_h, nullptr, p_base_h, out_h, nullptr, p_ln_h, 96, 96, 124);

    // ================= stage 3: per-pixel MLP with residual =================
    gemm_kernel<1, 1><<<gP3, 256>>>(mlp_w1, out_l, mlp_b1, nullptr, p_hbuf_l, nullptr, nullptr, 384, 96, 0);
    gemm_kernel<1, 1><<<gP3, 256>>>(mlp_w1, out_h, mlp_b1, nullptr, p_hbuf_h, nullptr, nullptr, 384, 96, 0);
    gemm_kernel<0, 2><<<gP1, 256>>>(mlp_w2, p_hbuf_l, mlp_b2, out_l, out_l, nullptr, nullptr, 96, 384, 0);
    gemm_kernel<0, 2><<<gP1, 256>>>(mlp_w2, p_hbuf_h, mlp_b2, out_h, out_h, nullptr, nullptr, 96, 384, 0);
}

// round 16
// speedup vs baseline: 1.2107x; 1.1075x over previous
#include <cuda_runtime.h>
#include <math.h>

#define BZ 2
#define CHN 96
#define HWSZ 16384              // 128*128
#define PTOT 32768              // B*H*W
#define TSZ 3145728             // C*B*H*W
#define NWD 31
#define SCALE_ATTN 0.2041241452319315f   // 1/sqrt(24)

// ---------------- device scratch (static; no allocations allowed) ----------------
__device__ float g_ln_l[TSZ];           // [c][b][hw]  (c-major)
__device__ float g_ln_h[TSZ];
__device__ float g_fold_l[TSZ];
__device__ float g_fold_h[TSZ];
__device__ float g_base_l[TSZ];         // [b][c][hw]  (b-major, like inputs/outputs)
__device__ float g_base_h[TSZ];
__device__ float g_qkv_l[288 * PTOT];   // rows: [0,96)=Q  [96,192)=K  [192,288)=V
__device__ float g_qkv_h[288 * PTOT];
__device__ float g_hbuf_l[384 * PTOT];  // MLP hidden (low),  c-major
__device__ float g_hbuf_h[384 * PTOT];  // MLP hidden (high), c-major
__device__ float g_pool[BZ * CHN];
__device__ float g_se[BZ * CHN];
__device__ float g_wl[288 * 96];        // stacked [Wq_l; Wk_l; Wv_l]
__device__ float g_wh[288 * 96];        // stacked [Wq_h; Wk_h; Wv_h]

// ---------------- LayerNorm (per pixel over 96 channels), optional +shift read ----
__global__ void ln_kernel(const float* __restrict__ src, float* __restrict__ dst,
                          const float* __restrict__ g, const float* __restrict__ bb, int shift) {
    int idx = blockIdx.x * 256 + threadIdx.x;      // 0..32767
    int b  = idx >> 14;
    int hw = idx & 16383;
    int h = hw >> 7, w = hw & 127;
    int hs = (h + shift) & 127, ws = (w + shift) & 127;
    const float* sp = src + (size_t)b * CHN * HWSZ + hs * 128 + ws;
    float sum = 0.f, sq = 0.f;
#pragma unroll 8
    for (int c = 0; c < CHN; c++) { float v = sp[(size_t)c * HWSZ]; sum += v; sq += v * v; }
    float mu  = sum * (1.f / 96.f);
    float var = sq * (1.f / 96.f) - mu * mu;
    float rs  = rsqrtf(var + 1e-5f);
    float* dp = dst + (size_t)b * HWSZ + hw;
#pragma unroll 8
    for (int c = 0; c < CHN; c++) {
        float v = sp[(size_t)c * HWSZ];
        dp[(size_t)c * PTOT] = (v - mu) * rs * g[c] + bb[c];
    }
}

// ---------------- SE: global average pool over HW per (b,c) ----------------------
__global__ void pool_kernel(const float* __restrict__ x, float* __restrict__ pool) {
    int bid = blockIdx.x;                 // b*96+c
    int b = bid / CHN, c = bid % CHN;
    const float* p = x + (size_t)c * PTOT + (size_t)b * HWSZ;
    float s = 0.f;
    for (int i = threadIdx.x; i < HWSZ; i += 256) s += p[i];
    __shared__ float red[8];
    for (int o = 16; o; o >>= 1) s += __shfl_xor_sync(0xffffffff, s, o);
    if ((threadIdx.x & 31) == 0) red[threadIdx.x >> 5] = s;
    __syncthreads();
    if (threadIdx.x == 0) {
        float t = 0.f;
        for (int i = 0; i < 8; i++) t += red[i];
        pool[bid] = t * (1.f / HWSZ);
    }
}

// ---------------- SE: squeeze-excite MLP (tiny) -----------------------------------
__global__ void se_kernel(const float* __restrict__ pool, const float* __restrict__ w1,
                          const float* __restrict__ w2, float* __restrict__ se) {
    __shared__ float z[12];               // [b][i][r]
    int t = threadIdx.x;
    if (t < 12) {
        int b = t / 6, rem = t % 6, i = rem >> 1, r = rem & 1;
        float a = 0.f;
        const float* pp = pool + b * 96 + i * 32;
        const float* wp = w1 + i * 64 + r * 32;
        for (int c = 0; c < 32; c++) a += pp[c] * wp[c];
        z[t] = fmaxf(a, 0.f);
    }
    __syncthreads();
    if (t < 192) {
        int b = t / 96, c = t % 96, i = c / 32, cl = c & 31;
        float v = z[b * 6 + i * 2 + 0] * w2[i * 64 + cl * 2 + 0]
                + z[b * 6 + i * 2 + 1] * w2[i * 64 + cl * 2 + 1];
        se[t] = 1.f / (1.f + __expf(-v));
    }
}

// ---------------- tiled GEMM: Y[O][P] = f(W[O][K] @ X[K][P]) ----------------------
// BM=96 (O), BN=128 (P), BK=16; 256 threads; 6x8 micro-tile, SPLIT-N (cols pc..pc+3
// and 64+pc..64+pc+3 -> 16B lane stride, conflict-free float4 LDS).
// Ws pitch 98: transposed stores hit 16 distinct even/odd banks per ol-parity (CF).
// 2-stage double buffer with register prefetch (R10-proven pipeline).
// O MUST be a multiple of 96; K a multiple of 16.
// XMODE: 0 = X c-major (opt per-(b,c) scale)    1 = X b-major
//        2 = X c-major read at shifted pixel, scaled by 1/cnt (window fold combine)
// YMODE: 0 = plain store c-major                1 = gelu(acc+bias) store c-major
//        2 = b-major: Y = res + acc (+bias) (+ lnadd at shifted pixel, c-major)
template <int XMODE, int YMODE>
__global__ void gemm_kernel(const float* __restrict__ W, const float* __restrict__ X,
                            const float* __restrict__ bias, const float* __restrict__ res,
                            float* __restrict__ Y, const float* __restrict__ scale,
                            const float* __restrict__ lnadd,
                            int O, int K, int shift) {
    __shared__ float Ws[2][16][98];     // [k][o], pitch 98 (CF transposed stores)
    __shared__ float Xs[2][16][132];    // [k][p]
    int t  = threadIdx.x;
    int og = t >> 4, pg = t & 15;       // og 0..15 (6 O-rows), pg 0..15 (4+4 cols)
    int og6 = og * 6, pc = pg * 4;
    int o0 = blockIdx.y * 96;
    int p0 = blockIdx.x * 128;

    float acc[6][8];
#pragma unroll
    for (int i = 0; i < 6; i++)
#pragma unroll
        for (int j = 0; j < 8; j++) acc[i][j] = 0.f;

    float wreg[6], xreg[8];

    // --- load tile (k0) into registers (coalesced gmem) ---
    auto load_regs = [&](int k0) {
#pragma unroll
        for (int r = 0; r < 6; r++) {
            int idx = t + r * 256;
            int ol = idx >> 4, kk = idx & 15;
            wreg[r] = W[(size_t)(o0 + ol) * K + k0 + kk];
        }
#pragma unroll
        for (int r = 0; r < 8; r++) {
            int idx = t + r * 256;
            int kk = idx >> 7, col = idx & 127;
            int p = p0 + col;
            int b = p >> 14, hw = p & 16383;
            int k = k0 + kk;
            float v;
            if (XMODE == 0) {
                v = X[(size_t)k * PTOT + p];
                if (scale) v *= scale[b * 96 + k];
            } else if (XMODE == 1) {
                v = X[((size_t)b * CHN + k) * HWSZ + hw];
            } else {
                int h = hw >> 7, w = hw & 127;
                int hs = (h + shift) & 127, wsp = (w + shift) & 127;
                int ch2 = (hs < 4 || hs >= 124) ? 1 : 2;
                int cw2 = (wsp < 4 || wsp >= 124) ? 1 : 2;
                float ic = 1.f / (float)(ch2 * cw2);
                v = X[(size_t)k * PTOT + (size_t)b * HWSZ + hs * 128 + wsp] * ic;
            }
            xreg[r] = v;
        }
    };
    // --- store registers into smem buffer buf ---
    auto store_smem = [&](int buf) {
#pragma unroll
        for (int r = 0; r < 6; r++) {
            int idx = t + r * 256;
            int ol = idx >> 4, kk = idx & 15;
            Ws[buf][kk][ol] = wreg[r];
        }
#pragma unroll
        for (int r = 0; r < 8; r++) {
            int idx = t + r * 256;
            int kk = idx >> 7, col = idx & 127;
            Xs[buf][kk][col] = xreg[r];
        }
    };

    load_regs(0);
    store_smem(0);
    __syncthreads();

    int nk = K >> 4;
    for (int it = 0; it < nk; it++) {
        int cur = it & 1;
        if (it + 1 < nk) load_regs((it + 1) << 4);   // LDGs overlap the FFMAs below
#pragma unroll
        for (int kk = 0; kk < 16; kk++) {
            float wv[6], xv[8];
            *(float2*)&wv[0] = *(const float2*)&Ws[cur][kk][og6];       // broadcast
            *(float2*)&wv[2] = *(const float2*)&Ws[cur][kk][og6 + 2];
            *(float2*)&wv[4] = *(const float2*)&Ws[cur][kk][og6 + 4];
            *(float4*)&xv[0] = *(const float4*)&Xs[cur][kk][pc];        // CF
            *(float4*)&xv[4] = *(const float4*)&Xs[cur][kk][64 + pc];   // CF
#pragma unroll
            for (int i = 0; i < 6; i++)
#pragma unroll
                for (int j = 0; j < 8; j++) acc[i][j] += wv[i] * xv[j];
        }
        if (it + 1 < nk) store_smem(cur ^ 1);
        __syncthreads();
    }

#pragma unroll
    for (int i = 0; i < 6; i++) {
        int o = o0 + og6 + i;
#pragma unroll
        for (int j = 0; j < 8; j++) {
            int p = p0 + (j < 4 ? pc + j : 64 + pc + (j - 4));
            float v = acc[i][j];
            if (YMODE == 0) {
                Y[(size_t)o * PTOT + p] = v;
            } else if (YMODE == 1) {
                v += bias[o];
                Y[(size_t)o * PTOT + p] = 0.5f * v * (1.f + erff(v * 0.70710678118654752f));
            } else {
                int b = p >> 14, hw = p & 16383;
                size_t a = ((size_t)b * CHN + o) * HWSZ + hw;
                if (bias) v += bias[o];
                if (lnadd) {
                    // _win returns LN(x) + proj(out); add LN at the same shifted pixel
                    int h = hw >> 7, w = hw & 127;
                    int hs2 = (h + shift) & 127, ws2 = (w + shift) & 127;
                    v += lnadd[(size_t)o * PTOT + (size_t)b * HWSZ + hs2 * 128 + ws2];
                }
                Y[a] = res[a] + v;
            }
        }
    }
}

// ---------------- window cross-attention -------------------------------------------
// One block = (window, batch, dir, head): blockIdx.z = dir*4 + head.
// q,k staged transposed [d][n] (pitch 68); v [m][d] (pitch 28); Ss pitch 65.
// SV uses all 256 threads: 4 d-groups of 6. Fold output via atomicAdd (R11-proven).
__global__ void attn_kernel(const float* __restrict__ qkv_l, const float* __restrict__ qkv_h,
                            float* __restrict__ fold_l, float* __restrict__ fold_h) {
    __shared__ float qst[24 * 68];  // [d][n]
    __shared__ float kst[24 * 68];  // [d][m]
    __shared__ float vs[64 * 28];   // [m][d]
    __shared__ float Ss[64 * 65];   // [n][m] pitch 65
    int t = threadIdx.x;
    int wid = blockIdx.x;           // 0..960
    int b = blockIdx.y;
    int dir = blockIdx.z >> 2;
    int hd  = blockIdx.z & 3;
    int h0 = (wid / NWD) * 4, w0 = (wid % NWD) * 4;
    int pixbase = b * HWSZ + h0 * 128 + w0;
    int rbase = hd * 24;

    const float* qsrc  = dir ? qkv_h : qkv_l;   // query side
    const float* kvsrc = dir ? qkv_l : qkv_h;   // key/value side
    float* fdst = dir ? fold_h : fold_l;

    // gather q,k (transposed) and v (row-major) — 6 elements per thread each
    for (int idx = t; idx < 1536; idx += 256) {
        int d = idx >> 6, n = idx & 63;
        int pix = pixbase + ((n >> 3) << 7) + (n & 7);
        qst[d * 68 + n] = qsrc[(size_t)(rbase + d) * PTOT + pix];        // stride-1 store
        kst[d * 68 + n] = kvsrc[(size_t)(96 + rbase + d) * PTOT + pix];  // stride-1 store
        vs[n * 28 + d]  = kvsrc[(size_t)(192 + rbase + d) * PTOT + pix];
    }
    __syncthreads();
    // scores S[n][m] = scale * sum_d q[d][n] k[d][m]; outer product per d
    {
        int nb = (t >> 4) << 2, mb = (t & 15) << 2;
        float acc[4][4];
#pragma unroll
        for (int i = 0; i < 4; i++)
#pragma unroll
            for (int j = 0; j < 4; j++) acc[i][j] = 0.f;
#pragma unroll 6
        for (int dc = 0; dc < 24; dc++) {
            float4 qv = *(const float4*)&qst[dc * 68 + nb];   // CF float4
            float4 kv = *(const float4*)&kst[dc * 68 + mb];   // CF float4
            float qa[4] = {qv.x, qv.y, qv.z, qv.w};
            float ka[4] = {kv.x, kv.y, kv.z, kv.w};
#pragma unroll
            for (int i = 0; i < 4; i++)
#pragma unroll
                for (int j = 0; j < 4; j++) acc[i][j] += qa[i] * ka[j];
        }
#pragma unroll
        for (int i = 0; i < 4; i++)
#pragma unroll
            for (int j = 0; j < 4; j++)
                Ss[(nb + i) * 65 + mb + j] = acc[i][j] * SCALE_ATTN;
    }
    __syncthreads();
    // softmax over m: 4 threads per row, shfl-reduce within lane-quad
    {
        int row = t >> 2, sub = t & 3;
        float* r = &Ss[row * 65];
        int m0 = sub * 16;
        float mx = -1e30f;
#pragma unroll
        for (int m = 0; m < 16; m++) mx = fmaxf(mx, r[m0 + m]);
        mx = fmaxf(mx, __shfl_xor_sync(0xffffffffu, mx, 1));
        mx = fmaxf(mx, __shfl_xor_sync(0xffffffffu, mx, 2));
        float sum = 0.f;
#pragma unroll
        for (int m = 0; m < 16; m++) {
            float e = __expf(r[m0 + m] - mx);
            r[m0 + m] = e; sum += e;
        }
        sum += __shfl_xor_sync(0xffffffffu, sum, 1);
        sum += __shfl_xor_sync(0xffffffffu, sum, 2);
        float inv = 1.f / sum;
#pragma unroll
        for (int m = 0; m < 16; m++) r[m0 + m] *= inv;
    }
    __syncthreads();
    // O[d][n] = sum_m S[n][m] v[m][d]; all 256 threads: (n, dgroup of 6)
    {
        int n = t & 63, dg = t >> 6;    // dg 0..3, d range dg*6..dg*6+5
        float a6[6];
#pragma unroll
        for (int i = 0; i < 6; i++) a6[i] = 0.f;
        const float* srow = &Ss[n * 65];
#pragma unroll 4
        for (int m = 0; m < 64; m++) {
            float s = srow[m];                       // CF (stride ≡ 1 bank)
            const float* vp = &vs[m * 28 + dg * 6];  // broadcast within warp
#pragma unroll
            for (int i = 0; i < 6; i++) a6[i] += s * vp[i];
        }
        int pix = pixbase + ((n >> 3) << 7) + (n & 7);
#pragma unroll
        for (int i = 0; i < 6; i++)
            atomicAdd(&fdst[(size_t)(rbase + dg * 6 + i) * PTOT + pix], a6[i]);
    }
}

// -------------------------------- host launcher -----------------------------------
extern "C" void kernel_launch(void* const* d_in, const int* in_sizes, int n_in,
                              void* d_out, int out_size) {
    const float* low    = (const float*)d_in[0];
    const float* high   = (const float*)d_in[1];
    const float* ln1_g  = (const float*)d_in[2];
    const float* ln1_b  = (const float*)d_in[3];
    const float* ln2_g  = (const float*)d_in[4];
    const float* ln2_b  = (const float*)d_in[5];
    const float* se_w1  = (const float*)d_in[6];
    const float* se_w2  = (const float*)d_in[7];
    const float* wq_l   = (const float*)d_in[8];
    const float* wk_h   = (const float*)d_in[9];
    const float* wv_h   = (const float*)d_in[10];
    const float* wq_h   = (const float*)d_in[11];
    const float* wk_l   = (const float*)d_in[12];
    const float* wv_l   = (const float*)d_in[13];
    const float* wp_l   = (const float*)d_in[14];
    const float* wp_h   = (const float*)d_in[15];
    const float* mlp_w1 = (const float*)d_in[16];
    const float* mlp_b1 = (const float*)d_in[17];
    const float* mlp_w2 = (const float*)d_in[18];
    const float* mlp_b2 = (const float*)d_in[19];

    float* out_l = (float*)d_out;
    float* out_h = out_l + (size_t)TSZ;

    float *p_ln_l, *p_ln_h, *p_fold_l, *p_fold_h, *p_base_l, *p_base_h;
    float *p_qkv_l, *p_qkv_h, *p_hbuf_l, *p_hbuf_h, *p_pool, *p_se, *p_wl, *p_wh;
    cudaGetSymbolAddress((void**)&p_ln_l,   g_ln_l);
    cudaGetSymbolAddress((void**)&p_ln_h,   g_ln_h);
    cudaGetSymbolAddress((void**)&p_fold_l, g_fold_l);
    cudaGetSymbolAddress((void**)&p_fold_h, g_fold_h);
    cudaGetSymbolAddress((void**)&p_base_l, g_base_l);
    cudaGetSymbolAddress((void**)&p_base_h, g_base_h);
    cudaGetSymbolAddress((void**)&p_qkv_l,  g_qkv_l);
    cudaGetSymbolAddress((void**)&p_qkv_h,  g_qkv_h);
    cudaGetSymbolAddress((void**)&p_hbuf_l, g_hbuf_l);
    cudaGetSymbolAddress((void**)&p_hbuf_h, g_hbuf_h);
    cudaGetSymbolAddress((void**)&p_pool,   g_pool);
    cudaGetSymbolAddress((void**)&p_se,     g_se);
    cudaGetSymbolAddress((void**)&p_wl,     g_wl);
    cudaGetSymbolAddress((void**)&p_wh,     g_wh);

    const size_t WB = 96 * 96 * sizeof(float);
    // stacked projection weights: [Q;K;V]
    cudaMemcpyAsync(p_wl,          wq_l, WB, cudaMemcpyDeviceToDevice, 0);
    cudaMemcpyAsync(p_wl + 9216,   wk_l, WB, cudaMemcpyDeviceToDevice, 0);
    cudaMemcpyAsync(p_wl + 18432,  wv_l, WB, cudaMemcpyDeviceToDevice, 0);
    cudaMemcpyAsync(p_wh,          wq_h, WB, cudaMemcpyDeviceToDevice, 0);
    cudaMemcpyAsync(p_wh + 9216,   wk_h, WB, cudaMemcpyDeviceToDevice, 0);
    cudaMemcpyAsync(p_wh + 18432,  wv_h, WB, cudaMemcpyDeviceToDevice, 0);

    cudaMemsetAsync(p_fold_l, 0, (size_t)TSZ * sizeof(float), 0);
    cudaMemsetAsync(p_fold_h, 0, (size_t)TSZ * sizeof(float), 0);

    dim3 gQKV(256, 3), gC96(256, 1), gMLP1(256, 4), gAttn(961, 2, 8);

    // ================= stage 1 (no shift) =================
    ln_kernel<<<128, 256>>>(low,  p_ln_l, ln1_g, ln1_b, 0);
    ln_kernel<<<128, 256>>>(high, p_ln_h, ln1_g, ln1_b, 0);
    gemm_kernel<0, 0><<<gQKV, 256>>>(p_wl, p_ln_l, nullptr, nullptr, p_qkv_l, nullptr, nullptr, 288, 96, 0);
    pool_kernel<<<192, 256>>>(p_ln_h, p_pool);
    se_kernel<<<1, 256>>>(p_pool, se_w1, se_w2, p_se);
    gemm_kernel<0, 0><<<gQKV, 256>>>(p_wh, p_ln_h, nullptr, nullptr, p_qkv_h, p_se, nullptr, 288, 96, 0);
    attn_kernel<<<gAttn, 256>>>(p_qkv_l, p_qkv_h, p_fold_l, p_fold_h);
    // base = input + LN(input) + proj(fold/cnt)
    gemm_kernel<2, 2><<<gC96, 256>>>(wp_l, p_fold_l, nullptr, low,  p_base_l, nullptr, p_ln_l, 96, 96, 0);
    gemm_kernel<2, 2><<<gC96, 256>>>(wp_h, p_fold_h, nullptr, high, p_base_h, nullptr, p_ln_h, 96, 96, 0);

    // ================= stage 2 (shifted by 4) =================
    ln_kernel<<<128, 256>>>(p_base_l, p_ln_l, ln2_g, ln2_b, 4);
    ln_kernel<<<128, 256>>>(p_base_h, p_ln_h, ln2_g, ln2_b, 4);
    pool_kernel<<<192, 256>>>(p_ln_h, p_pool);
    se_kernel<<<1, 256>>>(p_pool, se_w1, se_w2, p_se);
    gemm_kernel<0, 0><<<gQKV, 256>>>(p_wl, p_ln_l, nullptr, nullptr, p_qkv_l, nullptr, nullptr, 288, 96, 0);
    gemm_kernel<0, 0><<<gQKV, 256>>>(p_wh, p_ln_h, nullptr, nullptr, p_qkv_h, p_se, nullptr, 288, 96, 0);
    cudaMemsetAsync(p_fold_l, 0, (size_t)TSZ * sizeof(float), 0);
    cudaMemsetAsync(p_fold_h, 0, (size_t)TSZ * sizeof(float), 0);
    attn_kernel<<<gAttn, 256>>>(p_qkv_l, p_qkv_h, p_fold_l, p_fold_h);
    // un-shift: dst(h,w) = base + (LN(ls) + proj(fold/cnt))[(h-4)%128, (w-4)%128]
    gemm_kernel<2, 2><<<gC96, 256>>>(wp_l, p_fold_l, nullptr, p_base_l, out_l, nullptr, p_ln_l, 96, 96, 124);
    gemm_kernel<2, 2><<<gC96, 256>>>(wp_h, p_fold_h, nullptr, p_base_h, out_h, nullptr, p_ln_h, 96, 96, 124);

    // ================= stage 3: per-pixel MLP with residual =================
    gemm_kernel<1, 1><<<gMLP1, 256>>>(mlp_w1, out_l, mlp_b1, nullptr, p_hbuf_l, nullptr, nullptr, 384, 96, 0);
    gemm_kernel<1, 1><<<gMLP1, 256>>>(mlp_w1, out_h, mlp_b1, nullptr, p_hbuf_h, nullptr, nullptr, 384, 96, 0);
    gemm_kernel<0, 2><<<gC96, 256>>>(mlp_w2, p_hbuf_l, mlp_b2, out_l, out_l, nullptr, nullptr, 96, 384, 0);
    gemm_kernel<0, 2><<<gC96, 256>>>(mlp_w2, p_hbuf_h, mlp_b2, out_h, out_h, nullptr, nullptr, 96, 384, 0);
}